// round 1
// baseline (speedup 1.0000x reference)
#include <cuda_runtime.h>
#include <math.h>

#define D_MODEL 256
#define NHEAD   8
#define HEAD_DIM 32
#define B_SZ    4
#define N_SZ    256

// Scratch (no allocations allowed -> __device__ globals)
__device__ float g_Wt[D_MODEL * D_MODEL];          // W transposed: Wt[k*256+d] = W[d*256+k]
__device__ float g_node_p[B_SZ * N_SZ * D_MODEL];  // node projections
__device__ float g_out0[B_SZ * N_SZ * D_MODEL];    // attn @ V result (pre final proj)

// ---------------------------------------------------------------------------
// W transpose (tiny, runs once per launch)
// ---------------------------------------------------------------------------
__global__ void transpose_kernel(const float* __restrict__ W) {
    int o = blockIdx.x * 256 + threadIdx.x;    // o = k*256 + d  (coalesced writes)
    int k = o >> 8;
    int d = o & 255;
    g_Wt[o] = W[d * 256 + k];
}

// ---------------------------------------------------------------------------
// Shared GEMM tile body: computes acc[8][8] = A(64x256) @ Wt(256x256) for one
// 64-row tile. Thread (tx in [0,32), ty in [0,8)) owns rows jj*8+ty and
// columns u*32+tx  -> each thread holds exactly one lane (tx) of EVERY head u.
// Double-buffered smem, k-chunk = 16.
// ---------------------------------------------------------------------------
__device__ __forceinline__ void gemm_tile(const float* __restrict__ A, float acc[8][8]) {
    const int tid = threadIdx.x;
    const int tx = tid & 31;
    const int ty = tid >> 5;

    __shared__ float As[2][16][65];    // [kk][row], padded
    __shared__ float Ws[2][16][260];   // [kk][d],  padded (260 = 4-aligned)

#pragma unroll
    for (int a = 0; a < 8; a++)
#pragma unroll
        for (int c = 0; c < 8; c++) acc[a][c] = 0.0f;

    const int rowL = tid >> 2;  // 0..63
    const int kq   = tid & 3;   // 0..3 (which float4 within the 16-wide k chunk)

    // prologue: load chunk 0
    {
        float4 v = *(const float4*)(A + rowL * 256 + kq * 4);
        As[0][kq * 4 + 0][rowL] = v.x;
        As[0][kq * 4 + 1][rowL] = v.y;
        As[0][kq * 4 + 2][rowL] = v.z;
        As[0][kq * 4 + 3][rowL] = v.w;
#pragma unroll
        for (int c = 0; c < 4; c++) {
            int f = c * 256 + tid;
            int kk = f >> 6, d4 = f & 63;
            *(float4*)&Ws[0][kk][d4 * 4] = *(const float4*)(g_Wt + kk * 256 + d4 * 4);
        }
    }
    __syncthreads();

#pragma unroll 1
    for (int kt = 0; kt < 16; kt++) {
        const int cur = kt & 1;
        if (kt < 15) {
            const int nxt = cur ^ 1;
            const int k0 = (kt + 1) * 16;
            float4 v = *(const float4*)(A + rowL * 256 + k0 + kq * 4);
            As[nxt][kq * 4 + 0][rowL] = v.x;
            As[nxt][kq * 4 + 1][rowL] = v.y;
            As[nxt][kq * 4 + 2][rowL] = v.z;
            As[nxt][kq * 4 + 3][rowL] = v.w;
#pragma unroll
            for (int c = 0; c < 4; c++) {
                int f = c * 256 + tid;
                int kk = f >> 6, d4 = f & 63;
                *(float4*)&Ws[nxt][kk][d4 * 4] =
                    *(const float4*)(g_Wt + (k0 + kk) * 256 + d4 * 4);
            }
        }
#pragma unroll
        for (int kk = 0; kk < 16; kk++) {
            float a[8], w[8];
#pragma unroll
            for (int jj = 0; jj < 8; jj++) a[jj] = As[cur][kk][jj * 8 + ty];  // broadcast
#pragma unroll
            for (int u = 0; u < 8; u++) w[u] = Ws[cur][kk][u * 32 + tx];      // conflict-free
#pragma unroll
            for (int jj = 0; jj < 8; jj++)
#pragma unroll
                for (int u = 0; u < 8; u++)
                    acc[jj][u] = fmaf(a[jj], w[u], acc[jj][u]);
        }
        __syncthreads();
    }
}

// ---------------------------------------------------------------------------
// Node projection: g_node_p = nodes @ W^T + b
// ---------------------------------------------------------------------------
__global__ void __launch_bounds__(256, 2)
proj_nodes_kernel(const float* __restrict__ nodes, const float* __restrict__ bias) {
    float acc[8][8];
    gemm_tile(nodes + (size_t)blockIdx.x * 64 * 256, acc);
    const int tx = threadIdx.x & 31, ty = threadIdx.x >> 5;
#pragma unroll
    for (int jj = 0; jj < 8; jj++) {
        int r = blockIdx.x * 64 + jj * 8 + ty;
#pragma unroll
        for (int u = 0; u < 8; u++)
            g_node_p[r * 256 + u * 32 + tx] = acc[jj][u] + bias[u * 32 + tx];
    }
}

// ---------------------------------------------------------------------------
// Fused edge projection + scores. One block = one (b, i, 64-wide j tile).
// E = W*edges[b,i,j]+b stays in registers; scores computed in the epilogue:
//   score[h] = sum_{d in head h} (E+np_i)(E+np_j),  then 10*tanh(s/sqrt(32)).
// Written to the attn region of d_out (softmaxed in place next).
// ---------------------------------------------------------------------------
__global__ void __launch_bounds__(256, 2)
edge_score_kernel(const float* __restrict__ edges, const float* __restrict__ bias,
                  float* __restrict__ scores) {
    const int jt = blockIdx.x;  // j tile (0..3)
    const int i  = blockIdx.y;
    const int b  = blockIdx.z;
    const int tx = threadIdx.x & 31, ty = threadIdx.x >> 5;

    const float* A = edges + (((size_t)(b * N_SZ + i)) * N_SZ + jt * 64) * D_MODEL;
    float acc[8][8];
    gemm_tile(A, acc);

    float bia[8], npi[8];
    const float* npib = g_node_p + ((size_t)b * N_SZ + i) * D_MODEL;
#pragma unroll
    for (int u = 0; u < 8; u++) {
        bia[u] = bias[u * 32 + tx];
        npi[u] = npib[u * 32 + tx];
    }

#pragma unroll
    for (int jj = 0; jj < 8; jj++) {
        const int jg = jt * 64 + jj * 8 + ty;
        const float* npjb = g_node_p + ((size_t)b * N_SZ + jg) * D_MODEL;
        float s[8];
#pragma unroll
        for (int u = 0; u < 8; u++) {
            float E = acc[jj][u] + bia[u];
            s[u] = (E + npi[u]) * (E + npjb[u * 32 + tx]);
        }
#pragma unroll
        for (int off = 16; off > 0; off >>= 1)
#pragma unroll
            for (int u = 0; u < 8; u++)
                s[u] += __shfl_xor_sync(0xffffffffu, s[u], off);
        if (tx == 0) {
#pragma unroll
            for (int u = 0; u < 8; u++)
                scores[((((b * NHEAD + u) * N_SZ) + i) << 8) + jg] =
                    10.0f * tanhf(s[u] * 0.17677669529663687f);  // 1/sqrt(32)
        }
    }
}

// ---------------------------------------------------------------------------
// Softmax over j (in place in attn region) + out0 = attn @ node_p per head.
// One block per (b, h, i) row.
// ---------------------------------------------------------------------------
__global__ void softmax_av_kernel(float* __restrict__ attn) {
    const int i = blockIdx.x, h = blockIdx.y, b = blockIdx.z;
    const int tid = threadIdx.x;
    float* row = attn + ((((size_t)(b * NHEAD + h) * N_SZ) + i) << 8);

    __shared__ float sh[16];
    __shared__ float ps[256];
    __shared__ float red[8][33];

    float s = row[tid];
    float m = s;
#pragma unroll
    for (int off = 16; off > 0; off >>= 1)
        m = fmaxf(m, __shfl_xor_sync(0xffffffffu, m, off));
    if ((tid & 31) == 0) sh[tid >> 5] = m;
    __syncthreads();
    float bm = sh[0];
#pragma unroll
    for (int g = 1; g < 8; g++) bm = fmaxf(bm, sh[g]);

    float p = __expf(s - bm);
    float t = p;
#pragma unroll
    for (int off = 16; off > 0; off >>= 1)
        t += __shfl_xor_sync(0xffffffffu, t, off);
    if ((tid & 31) == 0) sh[8 + (tid >> 5)] = t;
    __syncthreads();
    float sum = 0.0f;
#pragma unroll
    for (int g = 0; g < 8; g++) sum += sh[8 + g];

    float a = p * (1.0f / sum);
    row[tid] = a;
    ps[tid] = a;
    __syncthreads();

    // out0[b,i,h*32+d] = sum_j attn[j] * node_p[b,j,h*32+d]
    const int d = tid & 31, g = tid >> 5;
    const float* np = g_node_p + (size_t)b * N_SZ * D_MODEL + h * 32 + d;
    float acc = 0.0f;
#pragma unroll
    for (int jj = 0; jj < 32; jj++) {
        int j = g * 32 + jj;
        acc = fmaf(ps[j], np[(size_t)j * 256], acc);
    }
    red[g][d] = acc;
    __syncthreads();
    if (tid < 32) {
        float o = 0.0f;
#pragma unroll
        for (int g2 = 0; g2 < 8; g2++) o += red[g2][tid];
        g_out0[((size_t)(b * N_SZ + i)) * D_MODEL + h * 32 + tid] = o;
    }
}

// ---------------------------------------------------------------------------
// Final projection: out = g_out0 @ W^T + b
// ---------------------------------------------------------------------------
__global__ void __launch_bounds__(256, 2)
proj_final_kernel(const float* __restrict__ bias, float* __restrict__ out) {
    float acc[8][8];
    gemm_tile(g_out0 + (size_t)blockIdx.x * 64 * 256, acc);
    const int tx = threadIdx.x & 31, ty = threadIdx.x >> 5;
#pragma unroll
    for (int jj = 0; jj < 8; jj++) {
        int r = blockIdx.x * 64 + jj * 8 + ty;
#pragma unroll
        for (int u = 0; u < 8; u++)
            out[r * 256 + u * 32 + tx] = acc[jj][u] + bias[u * 32 + tx];
    }
}

// ---------------------------------------------------------------------------
extern "C" void kernel_launch(void* const* d_in, const int* in_sizes, int n_in,
                              void* d_out, int out_size) {
    const float* nodes = (const float*)d_in[0];
    const float* edges = (const float*)d_in[1];
    const float* W     = (const float*)d_in[2];
    const float* bias  = (const float*)d_in[3];

    float* out  = (float*)d_out;
    float* attn = out + B_SZ * N_SZ * D_MODEL;  // tuple layout: (out, attn)

    transpose_kernel<<<256, 256>>>(W);
    proj_nodes_kernel<<<(B_SZ * N_SZ) / 64, 256>>>(nodes, bias);
    dim3 g2(N_SZ / 64, N_SZ, B_SZ);
    edge_score_kernel<<<g2, 256>>>(edges, bias, attn);
    dim3 g3(N_SZ, NHEAD, B_SZ);
    softmax_av_kernel<<<g3, 256>>>(attn);
    proj_final_kernel<<<(B_SZ * N_SZ) / 64, 256>>>(bias, out);
}

// round 3
// speedup vs baseline: 1.8734x; 1.8734x over previous
#include <cuda_runtime.h>
#include <cuda_bf16.h>
#include <math.h>
#include <stdint.h>

#define D_MODEL 256
#define NHEAD   8
#define HEAD_DIM 32
#define B_SZ    4
#define N_SZ    256

// ---------------- device scratch ----------------
__device__ float g_Wt[D_MODEL * D_MODEL];
__device__ float g_node_p[B_SZ * N_SZ * D_MODEL];
__device__ float g_out0[B_SZ * N_SZ * D_MODEL];
// W bf16 splits, pre-swizzled SW128 K-chunk tiles: 4 chunks x [256 n][64 k] (32KB each)
__device__ unsigned char g_WB_hi[131072];
__device__ unsigned char g_WB_lo[131072];

__device__ __forceinline__ uint32_t smem_u32(const void* p) {
    uint32_t a;
    asm("{ .reg .u64 t; cvta.to.shared.u64 t, %1; cvt.u32.u64 %0, t; }" : "=r"(a) : "l"(p));
    return a;
}

__device__ __forceinline__ void ldsm_x4(uint32_t r[4], uint32_t addr) {
    asm volatile("ldmatrix.sync.aligned.m8n8.x4.shared.b16 {%0,%1,%2,%3}, [%4];"
                 : "=r"(r[0]), "=r"(r[1]), "=r"(r[2]), "=r"(r[3]) : "r"(addr));
}

__device__ __forceinline__ void mma_bf16(float c[4], const uint32_t a[4], const uint32_t b[2]) {
    asm volatile(
        "mma.sync.aligned.m16n8k16.row.col.f32.bf16.bf16.f32 "
        "{%0,%1,%2,%3}, {%4,%5,%6,%7}, {%8,%9}, {%0,%1,%2,%3};"
        : "+f"(c[0]), "+f"(c[1]), "+f"(c[2]), "+f"(c[3])
        : "r"(a[0]), "r"(a[1]), "r"(a[2]), "r"(a[3]), "r"(b[0]), "r"(b[1]));
}

// ---------------- prep kernels ----------------
__global__ void transpose_kernel(const float* __restrict__ W) {
    int o = blockIdx.x * 256 + threadIdx.x;
    int k = o >> 8, d = o & 255;
    g_Wt[o] = W[d * 256 + k];
}

__global__ void wprep_kernel(const float* __restrict__ W) {
    int idx = blockIdx.x * 256 + threadIdx.x;  // d*256 + k   (W[d][k], N dim = d)
    int d = idx >> 8, k = idx & 255;
    float w = W[idx];
    __nv_bfloat16 h = __float2bfloat16_rn(w);
    float r = w - __bfloat162float(h);
    __nv_bfloat16 l = __float2bfloat16_rn(r);
    int chunk = k >> 6, kc = k & 63;
    int off = d * 128 + kc * 2;
    int sw = off ^ ((off >> 3) & 0x70);  // SW128: bits[7:10) -> [4:7)
    int pos = chunk * 32768 + sw;
    *(unsigned short*)(g_WB_hi + pos) = __bfloat16_as_ushort(h);
    *(unsigned short*)(g_WB_lo + pos) = __bfloat16_as_ushort(l);
}

// ---------------- fp32 tile GEMM for small projections ----------------
__device__ __forceinline__ void gemm_tile(const float* __restrict__ A, float acc[8][8]) {
    const int tid = threadIdx.x;
    const int tx = tid & 31;
    const int ty = tid >> 5;

    __shared__ float As[2][16][65];
    __shared__ float Ws[2][16][260];

#pragma unroll
    for (int a = 0; a < 8; a++)
#pragma unroll
        for (int c = 0; c < 8; c++) acc[a][c] = 0.0f;

    const int rowL = tid >> 2;
    const int kq = tid & 3;

    {
        float4 v = *(const float4*)(A + rowL * 256 + kq * 4);
        As[0][kq * 4 + 0][rowL] = v.x;
        As[0][kq * 4 + 1][rowL] = v.y;
        As[0][kq * 4 + 2][rowL] = v.z;
        As[0][kq * 4 + 3][rowL] = v.w;
#pragma unroll
        for (int c = 0; c < 4; c++) {
            int f = c * 256 + tid;
            int kk = f >> 6, d4 = f & 63;
            *(float4*)&Ws[0][kk][d4 * 4] = *(const float4*)(g_Wt + kk * 256 + d4 * 4);
        }
    }
    __syncthreads();

#pragma unroll 1
    for (int kt = 0; kt < 16; kt++) {
        const int cur = kt & 1;
        if (kt < 15) {
            const int nxt = cur ^ 1;
            const int k0 = (kt + 1) * 16;
            float4 v = *(const float4*)(A + rowL * 256 + k0 + kq * 4);
            As[nxt][kq * 4 + 0][rowL] = v.x;
            As[nxt][kq * 4 + 1][rowL] = v.y;
            As[nxt][kq * 4 + 2][rowL] = v.z;
            As[nxt][kq * 4 + 3][rowL] = v.w;
#pragma unroll
            for (int c = 0; c < 4; c++) {
                int f = c * 256 + tid;
                int kk = f >> 6, d4 = f & 63;
                *(float4*)&Ws[nxt][kk][d4 * 4] = *(const float4*)(g_Wt + (k0 + kk) * 256 + d4 * 4);
            }
        }
#pragma unroll
        for (int kk = 0; kk < 16; kk++) {
            float a[8], w[8];
#pragma unroll
            for (int jj = 0; jj < 8; jj++) a[jj] = As[cur][kk][jj * 8 + ty];
#pragma unroll
            for (int u = 0; u < 8; u++) w[u] = Ws[cur][kk][u * 32 + tx];
#pragma unroll
            for (int jj = 0; jj < 8; jj++)
#pragma unroll
                for (int u = 0; u < 8; u++)
                    acc[jj][u] = fmaf(a[jj], w[u], acc[jj][u]);
        }
        __syncthreads();
    }
}

__global__ void __launch_bounds__(256, 2)
proj_nodes_kernel(const float* __restrict__ nodes, const float* __restrict__ bias) {
    float acc[8][8];
    gemm_tile(nodes + (size_t)blockIdx.x * 64 * 256, acc);
    const int tx = threadIdx.x & 31, ty = threadIdx.x >> 5;
#pragma unroll
    for (int jj = 0; jj < 8; jj++) {
        int r = blockIdx.x * 64 + jj * 8 + ty;
#pragma unroll
        for (int u = 0; u < 8; u++)
            g_node_p[r * 256 + u * 32 + tx] = acc[jj][u] + bias[u * 32 + tx];
    }
}

__global__ void __launch_bounds__(256, 2)
proj_final_kernel(const float* __restrict__ bias, float* __restrict__ out) {
    float acc[8][8];
    gemm_tile(g_out0 + (size_t)blockIdx.x * 64 * 256, acc);
    const int tx = threadIdx.x & 31, ty = threadIdx.x >> 5;
#pragma unroll
    for (int jj = 0; jj < 8; jj++) {
        int r = blockIdx.x * 64 + jj * 8 + ty;
#pragma unroll
        for (int u = 0; u < 8; u++)
            out[r * 256 + u * 32 + tx] = acc[jj][u] + bias[u * 32 + tx];
    }
}

// ---------------- edge projection + scores via warp MMA ----------------
// SMEM: A_hi [128][256]bf16 (512B rows, swizzled)  @ 0       (64KB)
//       A_lo                                        @ 65536   (64KB)
//       W_hi chunk [256 n][64 k] bf16 SW128         @ 131072  (32KB)
//       W_lo chunk                                  @ 163840  (32KB)
#define SM_AHI 0
#define SM_ALO 65536
#define SM_WH  131072
#define SM_WL  163840
#define SM_DYN 196608

__device__ __forceinline__ void copyW_async(uint32_t smb, int c) {
    const int t = threadIdx.x;
    unsigned long long sh = (unsigned long long)__cvta_generic_to_global(g_WB_hi) + c * 32768;
    unsigned long long sl = (unsigned long long)__cvta_generic_to_global(g_WB_lo) + c * 32768;
    uint32_t dh = smb + SM_WH, dl = smb + SM_WL;
#pragma unroll
    for (int q = 0; q < 8; q++) {
        int off = (q * 256 + t) * 16;
        asm volatile("cp.async.cg.shared.global [%0], [%1], 16;" :: "r"(dh + off), "l"(sh + off));
        asm volatile("cp.async.cg.shared.global [%0], [%1], 16;" :: "r"(dl + off), "l"(sl + off));
    }
    asm volatile("cp.async.commit_group;" ::: "memory");
}

__global__ void __launch_bounds__(256, 1)
edge_score_mma(const float* __restrict__ edges, const float* __restrict__ bias,
               float* __restrict__ scores) {
    extern __shared__ char sm[];
    const uint32_t smb = smem_u32(sm);
    const int tid = threadIdx.x, wid = tid >> 5, lane = tid & 31;
    const int jt = blockIdx.x, i = blockIdx.y, b = blockIdx.z;
    const int wm = (wid >> 2) * 64, wn = (wid & 3) * 64;

    copyW_async(smb, 0);  // overlap W chunk 0 with A conversion

    // ---- A: load fp32, split hi/lo bf16, store swizzled ----
    const float* A = edges + ((((size_t)b * N_SZ + i) * N_SZ) + (size_t)jt * 128) * D_MODEL;
    {
        const int r0 = tid >> 3;  // 0..31
        const int l8 = tid & 7;   // 0..7
#pragma unroll
        for (int rp = 0; rp < 4; rp++) {
            int row = rp * 32 + r0;
            const float4* src = (const float4*)(A + (size_t)row * 256);
#pragma unroll
            for (int g = 0; g < 8; g++) {
                int c4 = g * 8 + l8;
                float4 v = src[c4];
                __nv_bfloat16 hx = __float2bfloat16_rn(v.x);
                __nv_bfloat16 hy = __float2bfloat16_rn(v.y);
                __nv_bfloat16 hz = __float2bfloat16_rn(v.z);
                __nv_bfloat16 hw = __float2bfloat16_rn(v.w);
                __nv_bfloat16 lx = __float2bfloat16_rn(v.x - __bfloat162float(hx));
                __nv_bfloat16 ly = __float2bfloat16_rn(v.y - __bfloat162float(hy));
                __nv_bfloat16 lz = __float2bfloat16_rn(v.z - __bfloat162float(hz));
                __nv_bfloat16 lw = __float2bfloat16_rn(v.w - __bfloat162float(hw));
                uint2 hi2, lo2;
                hi2.x = (uint32_t)__bfloat16_as_ushort(hx) | ((uint32_t)__bfloat16_as_ushort(hy) << 16);
                hi2.y = (uint32_t)__bfloat16_as_ushort(hz) | ((uint32_t)__bfloat16_as_ushort(hw) << 16);
                lo2.x = (uint32_t)__bfloat16_as_ushort(lx) | ((uint32_t)__bfloat16_as_ushort(ly) << 16);
                lo2.y = (uint32_t)__bfloat16_as_ushort(lz) | ((uint32_t)__bfloat16_as_ushort(lw) << 16);
                int off = row * 512 + c4 * 8;
                int sw = off ^ ((off >> 5) & 0x70);  // 512B rows: bits[9:12) -> [4:7)
                *(uint2*)(sm + SM_AHI + sw) = hi2;
                *(uint2*)(sm + SM_ALO + sw) = lo2;
            }
        }
    }
    asm volatile("cp.async.wait_group 0;" ::: "memory");
    __syncthreads();

    float acc[4][8][4];
#pragma unroll
    for (int mf = 0; mf < 4; mf++)
#pragma unroll
        for (int nf = 0; nf < 8; nf++)
#pragma unroll
            for (int c = 0; c < 4; c++) acc[mf][nf][c] = 0.0f;

    // per-lane ldmatrix address constants
    uint32_t apre[4], axor[4];
#pragma unroll
    for (int mf = 0; mf < 4; mf++) {
        int row = wm + mf * 16 + (lane & 15);
        apre[mf] = row * 512;
        axor[mf] = (row & 7) << 4;
    }
    const int koffA = (lane >> 4) * 8;
    uint32_t bpre[4], bxor[4];
#pragma unroll
    for (int gb = 0; gb < 4; gb++) {
        int n = wn + gb * 16 + (((lane >> 3) >= 2) ? 8 : 0) + (lane & 7);
        bpre[gb] = n * 128;
        bxor[gb] = (n & 7) << 4;
    }
    const int kcB = ((lane >> 3) & 1) * 8;

#pragma unroll 1
    for (int ch = 0; ch < 4; ch++) {
#pragma unroll
        for (int ks = 0; ks < 4; ks++) {
            const uint32_t kg2 = (uint32_t)((ch * 64 + ks * 16 + koffA) * 2);
            uint32_t ah[4][4], al[4][4];
#pragma unroll
            for (int mf = 0; mf < 4; mf++) {
                uint32_t ad = smb + SM_AHI + apre[mf] + (kg2 ^ axor[mf]);
                ldsm_x4(ah[mf], ad);
                ldsm_x4(al[mf], ad + (SM_ALO - SM_AHI));
            }
            const uint32_t kc2 = (uint32_t)((ks * 16 + kcB) * 2);
            uint32_t bh[4][4], bl[4][4];
#pragma unroll
            for (int gb = 0; gb < 4; gb++) {
                uint32_t bd = smb + SM_WH + bpre[gb] + (kc2 ^ bxor[gb]);
                ldsm_x4(bh[gb], bd);
                ldsm_x4(bl[gb], bd + (SM_WL - SM_WH));
            }
#pragma unroll
            for (int mf = 0; mf < 4; mf++)
#pragma unroll
                for (int nf = 0; nf < 8; nf++) {
                    const uint32_t* ph = &bh[nf >> 1][(nf & 1) * 2];
                    const uint32_t* pl = &bl[nf >> 1][(nf & 1) * 2];
                    mma_bf16(acc[mf][nf], ah[mf], ph);
                    mma_bf16(acc[mf][nf], ah[mf], pl);
                    mma_bf16(acc[mf][nf], al[mf], ph);
                }
        }
        __syncthreads();
        if (ch < 3) {
            copyW_async(smb, ch + 1);
            asm volatile("cp.async.wait_group 0;" ::: "memory");
            __syncthreads();
        }
    }

    // ---- epilogue: stage np_j tile (fp32, stride 260 to dodge conflicts) ----
    {
        float* nps = (float*)sm;
        const float* src = g_node_p + ((size_t)b * N_SZ + jt * 128) * 256;
        int row = tid >> 1, half = tid & 1;
        const float4* s4 = (const float4*)(src + (size_t)row * 256) + half * 32;
        float4* d4 = (float4*)(nps + row * 260) + half * 32;
#pragma unroll
        for (int q = 0; q < 32; q++) d4[q] = s4[q];
    }
    __syncthreads();

    float pb[16], p1[16];
    {
        const float* npi = g_node_p + ((size_t)b * N_SZ + i) * 256;
#pragma unroll
        for (int h = 0; h < 2; h++)
#pragma unroll
            for (int nf = 0; nf < 4; nf++)
#pragma unroll
                for (int v = 0; v < 2; v++) {
                    int idx = h * 8 + nf * 2 + v;
                    int d = wn + (h * 4 + nf) * 8 + (lane & 3) * 2 + v;
                    float bv = bias[d];
                    pb[idx] = bv;
                    p1[idx] = bv + npi[d];
                }
    }

    const float* nps = (const float*)sm;
#pragma unroll
    for (int mf = 0; mf < 4; mf++) {
#pragma unroll
        for (int half = 0; half < 2; half++) {
            int r = wm + mf * 16 + (lane >> 2) + half * 8;
            const float* nj = nps + r * 260 + wn;
#pragma unroll
            for (int h = 0; h < 2; h++) {
                float s = 0.0f;
#pragma unroll
                for (int nf = 0; nf < 4; nf++)
#pragma unroll
                    for (int v = 0; v < 2; v++) {
                        int idx = h * 8 + nf * 2 + v;
                        float a = acc[mf][h * 4 + nf][half * 2 + v];
                        float njv = nj[(h * 4 + nf) * 8 + (lane & 3) * 2 + v];
                        s += (a + p1[idx]) * (a + pb[idx] + njv);
                    }
                s += __shfl_xor_sync(0xffffffffu, s, 1);
                s += __shfl_xor_sync(0xffffffffu, s, 2);
                if ((lane & 3) == 0) {
                    int hg = (wn >> 5) + h;
                    scores[((((size_t)b * NHEAD + hg) * N_SZ + i) << 8) + jt * 128 + r] =
                        10.0f * tanhf(s * 0.17677669529663687f);
                }
            }
        }
    }
}

// ---------------- softmax + AV ----------------
__global__ void softmax_av_kernel(float* __restrict__ attn) {
    const int i = blockIdx.x, h = blockIdx.y, b = blockIdx.z;
    const int tid = threadIdx.x;
    float* row = attn + ((((size_t)(b * NHEAD + h) * N_SZ) + i) << 8);

    __shared__ float sh[16];
    __shared__ float ps[256];
    __shared__ float red[8][33];

    float s = row[tid];
    float m = s;
#pragma unroll
    for (int off = 16; off > 0; off >>= 1)
        m = fmaxf(m, __shfl_xor_sync(0xffffffffu, m, off));
    if ((tid & 31) == 0) sh[tid >> 5] = m;
    __syncthreads();
    float bm = sh[0];
#pragma unroll
    for (int g = 1; g < 8; g++) bm = fmaxf(bm, sh[g]);

    float p = __expf(s - bm);
    float t = p;
#pragma unroll
    for (int off = 16; off > 0; off >>= 1)
        t += __shfl_xor_sync(0xffffffffu, t, off);
    if ((tid & 31) == 0) sh[8 + (tid >> 5)] = t;
    __syncthreads();
    float sum = 0.0f;
#pragma unroll
    for (int g = 0; g < 8; g++) sum += sh[8 + g];

    float a = p * (1.0f / sum);
    row[tid] = a;
    ps[tid] = a;
    __syncthreads();

    const int d = tid & 31, g = tid >> 5;
    const float* np = g_node_p + (size_t)b * N_SZ * D_MODEL + h * 32 + d;
    float acc = 0.0f;
#pragma unroll
    for (int jj = 0; jj < 32; jj++) {
        int j = g * 32 + jj;
        acc = fmaf(ps[j], np[(size_t)j * 256], acc);
    }
    red[g][d] = acc;
    __syncthreads();
    if (tid < 32) {
        float o = 0.0f;
#pragma unroll
        for (int g2 = 0; g2 < 8; g2++) o += red[g2][tid];
        g_out0[((size_t)(b * N_SZ + i)) * D_MODEL + h * 32 + tid] = o;
    }
}

// ---------------- launch ----------------
extern "C" void kernel_launch(void* const* d_in, const int* in_sizes, int n_in,
                              void* d_out, int out_size) {
    const float* nodes = (const float*)d_in[0];
    const float* edges = (const float*)d_in[1];
    const float* W     = (const float*)d_in[2];
    const float* bias  = (const float*)d_in[3];

    float* out  = (float*)d_out;
    float* attn = out + B_SZ * N_SZ * D_MODEL;

    cudaFuncSetAttribute(edge_score_mma, cudaFuncAttributeMaxDynamicSharedMemorySize, SM_DYN);

    transpose_kernel<<<256, 256>>>(W);
    wprep_kernel<<<256, 256>>>(W);
    proj_nodes_kernel<<<(B_SZ * N_SZ) / 64, 256>>>(nodes, bias);
    dim3 g2(2, N_SZ, B_SZ);
    edge_score_mma<<<g2, 256, SM_DYN>>>(edges, bias, attn);
    dim3 g3(N_SZ, NHEAD, B_SZ);
    softmax_av_kernel<<<g3, 256>>>(attn);
    proj_final_kernel<<<(B_SZ * N_SZ) / 64, 256>>>(bias, out);
}

// round 4
// speedup vs baseline: 1.9720x; 1.0526x over previous
#include <cuda_runtime.h>
#include <cuda_bf16.h>
#include <math.h>
#include <stdint.h>

#define D_MODEL 256
#define NHEAD   8
#define HEAD_DIM 32
#define B_SZ    4
#define N_SZ    256

// ---------------- device scratch ----------------
__device__ float g_Wt[D_MODEL * D_MODEL];
__device__ float g_node_p[B_SZ * N_SZ * D_MODEL];
__device__ float g_out0[B_SZ * N_SZ * D_MODEL];
// W bf16 splits, pre-swizzled SW128 K-chunk tiles: 4 chunks x [256 n][64 k] (32KB each)
__device__ unsigned char g_WB_hi[131072];
__device__ unsigned char g_WB_lo[131072];

__device__ __forceinline__ uint32_t smem_u32(const void* p) {
    uint32_t a;
    asm("{ .reg .u64 t; cvta.to.shared.u64 t, %1; cvt.u32.u64 %0, t; }" : "=r"(a) : "l"(p));
    return a;
}

__device__ __forceinline__ void ldsm_x4(uint32_t r[4], uint32_t addr) {
    asm volatile("ldmatrix.sync.aligned.m8n8.x4.shared.b16 {%0,%1,%2,%3}, [%4];"
                 : "=r"(r[0]), "=r"(r[1]), "=r"(r[2]), "=r"(r[3]) : "r"(addr));
}

__device__ __forceinline__ void mma_bf16(float c[4], const uint32_t a[4], const uint32_t b[2]) {
    asm volatile(
        "mma.sync.aligned.m16n8k16.row.col.f32.bf16.bf16.f32 "
        "{%0,%1,%2,%3}, {%4,%5,%6,%7}, {%8,%9}, {%0,%1,%2,%3};"
        : "+f"(c[0]), "+f"(c[1]), "+f"(c[2]), "+f"(c[3])
        : "r"(a[0]), "r"(a[1]), "r"(a[2]), "r"(a[3]), "r"(b[0]), "r"(b[1]));
}

// ---------------- prep: W transpose + bf16 split/swizzle (merged) ----------------
__global__ void wprep_kernel(const float* __restrict__ W) {
    int idx = blockIdx.x * 256 + threadIdx.x;  // d*256 + k
    int d = idx >> 8, k = idx & 255;
    float w = W[idx];
    g_Wt[k * 256 + d] = w;  // transpose for fp32 helper gemms
    __nv_bfloat16 h = __float2bfloat16_rn(w);
    float r = w - __bfloat162float(h);
    __nv_bfloat16 l = __float2bfloat16_rn(r);
    int chunk = k >> 6, kc = k & 63;
    int off = d * 128 + kc * 2;
    int sw = off ^ ((off >> 3) & 0x70);
    int pos = chunk * 32768 + sw;
    *(unsigned short*)(g_WB_hi + pos) = __bfloat16_as_ushort(h);
    *(unsigned short*)(g_WB_lo + pos) = __bfloat16_as_ushort(l);
}

// ---------------- fp32 tile GEMM for small projections ----------------
__device__ __forceinline__ void gemm_tile(const float* __restrict__ A, float acc[8][8]) {
    const int tid = threadIdx.x;
    const int tx = tid & 31;
    const int ty = tid >> 5;

    __shared__ float As[2][16][65];
    __shared__ float Ws[2][16][260];

#pragma unroll
    for (int a = 0; a < 8; a++)
#pragma unroll
        for (int c = 0; c < 8; c++) acc[a][c] = 0.0f;

    const int rowL = tid >> 2;
    const int kq = tid & 3;

    {
        float4 v = *(const float4*)(A + rowL * 256 + kq * 4);
        As[0][kq * 4 + 0][rowL] = v.x;
        As[0][kq * 4 + 1][rowL] = v.y;
        As[0][kq * 4 + 2][rowL] = v.z;
        As[0][kq * 4 + 3][rowL] = v.w;
#pragma unroll
        for (int c = 0; c < 4; c++) {
            int f = c * 256 + tid;
            int kk = f >> 6, d4 = f & 63;
            *(float4*)&Ws[0][kk][d4 * 4] = *(const float4*)(g_Wt + kk * 256 + d4 * 4);
        }
    }
    __syncthreads();

#pragma unroll 1
    for (int kt = 0; kt < 16; kt++) {
        const int cur = kt & 1;
        if (kt < 15) {
            const int nxt = cur ^ 1;
            const int k0 = (kt + 1) * 16;
            float4 v = *(const float4*)(A + rowL * 256 + k0 + kq * 4);
            As[nxt][kq * 4 + 0][rowL] = v.x;
            As[nxt][kq * 4 + 1][rowL] = v.y;
            As[nxt][kq * 4 + 2][rowL] = v.z;
            As[nxt][kq * 4 + 3][rowL] = v.w;
#pragma unroll
            for (int c = 0; c < 4; c++) {
                int f = c * 256 + tid;
                int kk = f >> 6, d4 = f & 63;
                *(float4*)&Ws[nxt][kk][d4 * 4] = *(const float4*)(g_Wt + (k0 + kk) * 256 + d4 * 4);
            }
        }
#pragma unroll
        for (int kk = 0; kk < 16; kk++) {
            float a[8], w[8];
#pragma unroll
            for (int jj = 0; jj < 8; jj++) a[jj] = As[cur][kk][jj * 8 + ty];
#pragma unroll
            for (int u = 0; u < 8; u++) w[u] = Ws[cur][kk][u * 32 + tx];
#pragma unroll
            for (int jj = 0; jj < 8; jj++)
#pragma unroll
                for (int u = 0; u < 8; u++)
                    acc[jj][u] = fmaf(a[jj], w[u], acc[jj][u]);
        }
        __syncthreads();
    }
}

__global__ void __launch_bounds__(256, 2)
proj_nodes_kernel(const float* __restrict__ nodes, const float* __restrict__ bias) {
    float acc[8][8];
    gemm_tile(nodes + (size_t)blockIdx.x * 64 * 256, acc);
    const int tx = threadIdx.x & 31, ty = threadIdx.x >> 5;
#pragma unroll
    for (int jj = 0; jj < 8; jj++) {
        int r = blockIdx.x * 64 + jj * 8 + ty;
#pragma unroll
        for (int u = 0; u < 8; u++)
            g_node_p[r * 256 + u * 32 + tx] = acc[jj][u] + bias[u * 32 + tx];
    }
}

__global__ void __launch_bounds__(256, 2)
proj_final_kernel(const float* __restrict__ bias, float* __restrict__ out) {
    float acc[8][8];
    gemm_tile(g_out0 + (size_t)blockIdx.x * 64 * 256, acc);
    const int tx = threadIdx.x & 31, ty = threadIdx.x >> 5;
#pragma unroll
    for (int jj = 0; jj < 8; jj++) {
        int r = blockIdx.x * 64 + jj * 8 + ty;
#pragma unroll
        for (int u = 0; u < 8; u++)
            out[r * 256 + u * 32 + tx] = acc[jj][u] + bias[u * 32 + tx];
    }
}

// ---------------- edge projection + scores via warp MMA, fully pipelined ----------------
// SMEM: A slots: 2 x (16KB hi + 16KB lo)  @ 0        (64KB)   [128 rows x 64 k bf16, SW128]
//       W slots: 2 x (32KB hi + 32KB lo)  @ 65536    (128KB)  [256 n x 64 k bf16, SW128]
#define SM_A   0
#define SM_W   65536
#define SM_DYN 196608

__device__ __forceinline__ void copyW_async(uint32_t smb, int c, int slot) {
    const int t = threadIdx.x;
    unsigned long long sh = (unsigned long long)__cvta_generic_to_global(g_WB_hi) + c * 32768;
    unsigned long long sl = (unsigned long long)__cvta_generic_to_global(g_WB_lo) + c * 32768;
    uint32_t dh = smb + SM_W + slot * 65536;
    uint32_t dl = dh + 32768;
#pragma unroll
    for (int q = 0; q < 8; q++) {
        int off = (q * 256 + t) * 16;
        asm volatile("cp.async.cg.shared.global [%0], [%1], 16;" :: "r"(dh + off), "l"(sh + off));
        asm volatile("cp.async.cg.shared.global [%0], [%1], 16;" :: "r"(dl + off), "l"(sl + off));
    }
    asm volatile("cp.async.commit_group;" ::: "memory");
}

// convert one float4 of A-chunk data and store hi/lo swizzled into A slot
__device__ __forceinline__ void cvt_store_a(char* sm, int slot, int flat, float4 v) {
    __nv_bfloat16 hx = __float2bfloat16_rn(v.x);
    __nv_bfloat16 hy = __float2bfloat16_rn(v.y);
    __nv_bfloat16 hz = __float2bfloat16_rn(v.z);
    __nv_bfloat16 hw = __float2bfloat16_rn(v.w);
    __nv_bfloat16 lx = __float2bfloat16_rn(v.x - __bfloat162float(hx));
    __nv_bfloat16 ly = __float2bfloat16_rn(v.y - __bfloat162float(hy));
    __nv_bfloat16 lz = __float2bfloat16_rn(v.z - __bfloat162float(hz));
    __nv_bfloat16 lw = __float2bfloat16_rn(v.w - __bfloat162float(hw));
    uint2 hi2, lo2;
    hi2.x = (uint32_t)__bfloat16_as_ushort(hx) | ((uint32_t)__bfloat16_as_ushort(hy) << 16);
    hi2.y = (uint32_t)__bfloat16_as_ushort(hz) | ((uint32_t)__bfloat16_as_ushort(hw) << 16);
    lo2.x = (uint32_t)__bfloat16_as_ushort(lx) | ((uint32_t)__bfloat16_as_ushort(ly) << 16);
    lo2.y = (uint32_t)__bfloat16_as_ushort(lz) | ((uint32_t)__bfloat16_as_ushort(lw) << 16);
    int row = flat >> 4, c4 = flat & 15;
    int off = row * 128 + c4 * 8;
    int sw = off ^ ((off >> 3) & 0x70);
    char* base = sm + SM_A + slot * 32768;
    *(uint2*)(base + sw) = hi2;
    *(uint2*)(base + 16384 + sw) = lo2;
}

__global__ void __launch_bounds__(256, 1)
edge_score_mma(const float* __restrict__ edges, const float* __restrict__ bias,
               float* __restrict__ scores) {
    extern __shared__ char sm[];
    const uint32_t smb = smem_u32(sm);
    const int tid = threadIdx.x, wid = tid >> 5, lane = tid & 31;
    const int jt = blockIdx.x, i = blockIdx.y, b = blockIdx.z;
    const int wm = (wid >> 2) * 64, wn = (wid & 3) * 64;

    const float* A = edges + ((((size_t)b * N_SZ + i) * N_SZ) + (size_t)jt * 128) * D_MODEL;

    // ---- prologue: W chunk 0 (async) + A chunk 0 (convert) ----
    copyW_async(smb, 0, 0);
    {
#pragma unroll
        for (int q = 0; q < 8; q++) {
            int flat = q * 256 + tid;
            int row = flat >> 4, c4 = flat & 15;
            float4 v = *(const float4*)(A + (size_t)row * 256 + c4 * 4);
            cvt_store_a(sm, 0, flat, v);
        }
    }
    asm volatile("cp.async.wait_group 0;" ::: "memory");
    __syncthreads();

    float acc[4][8][4];
#pragma unroll
    for (int mf = 0; mf < 4; mf++)
#pragma unroll
        for (int nf = 0; nf < 8; nf++)
#pragma unroll
            for (int c = 0; c < 4; c++) acc[mf][nf][c] = 0.0f;

    // per-lane ldmatrix address constants (A rows now 128B, chunk-local k)
    uint32_t apre[4], axor[4];
#pragma unroll
    for (int mf = 0; mf < 4; mf++) {
        int row = wm + mf * 16 + (lane & 15);
        apre[mf] = row * 128;
        axor[mf] = (row & 7) << 4;
    }
    const int koffA = (lane >> 4) * 8;
    uint32_t bpre[4], bxor[4];
#pragma unroll
    for (int gb = 0; gb < 4; gb++) {
        int n = wn + gb * 16 + (((lane >> 3) >= 2) ? 8 : 0) + (lane & 7);
        bpre[gb] = n * 128;
        bxor[gb] = (n & 7) << 4;
    }
    const int kcB = ((lane >> 3) & 1) * 8;

#pragma unroll 1
    for (int ch = 0; ch < 4; ch++) {
        const int cur = ch & 1, nxt = cur ^ 1;
        if (ch < 3) copyW_async(smb, ch + 1, nxt);
        const uint32_t abase = smb + SM_A + cur * 32768;
        const uint32_t wbase = smb + SM_W + cur * 65536;
        const float* Anext = A + (ch + 1) * 64;

#pragma unroll
        for (int ks = 0; ks < 4; ks++) {
            // prefetch next-chunk A fp32 (2 float4/thread/ks)
            float4 v0, v1;
            int f0 = (2 * ks) * 256 + tid, f1 = f0 + 256;
            if (ch < 3) {
                v0 = *(const float4*)(Anext + (size_t)(f0 >> 4) * 256 + (f0 & 15) * 4);
                v1 = *(const float4*)(Anext + (size_t)(f1 >> 4) * 256 + (f1 & 15) * 4);
            }

            const uint32_t kg2 = (uint32_t)((ks * 16 + koffA) * 2);
            uint32_t ah[4][4], al[4][4];
#pragma unroll
            for (int mf = 0; mf < 4; mf++) {
                uint32_t ad = abase + apre[mf] + (kg2 ^ axor[mf]);
                ldsm_x4(ah[mf], ad);
                ldsm_x4(al[mf], ad + 16384);
            }
            const uint32_t kc2 = (uint32_t)((ks * 16 + kcB) * 2);
            uint32_t bh[4][4], bl[4][4];
#pragma unroll
            for (int gb = 0; gb < 4; gb++) {
                uint32_t bd = wbase + bpre[gb] + (kc2 ^ bxor[gb]);
                ldsm_x4(bh[gb], bd);
                ldsm_x4(bl[gb], bd + 32768);
            }
#pragma unroll
            for (int mf = 0; mf < 4; mf++)
#pragma unroll
                for (int nf = 0; nf < 8; nf++) {
                    const uint32_t* ph = &bh[nf >> 1][(nf & 1) * 2];
                    const uint32_t* pl = &bl[nf >> 1][(nf & 1) * 2];
                    mma_bf16(acc[mf][nf], ah[mf], ph);
                    mma_bf16(acc[mf][nf], ah[mf], pl);
                    mma_bf16(acc[mf][nf], al[mf], ph);
                }

            if (ch < 3) {
                cvt_store_a(sm, nxt, f0, v0);
                cvt_store_a(sm, nxt, f1, v1);
            }
        }
        asm volatile("cp.async.wait_group 0;" ::: "memory");
        __syncthreads();
    }

    // ---- epilogue: stage np_j tile (fp32, stride 260 to dodge conflicts) ----
    {
        float* nps = (float*)sm;
        const float* src = g_node_p + ((size_t)b * N_SZ + jt * 128) * 256;
        int row = tid >> 1, half = tid & 1;
        const float4* s4 = (const float4*)(src + (size_t)row * 256) + half * 32;
        float4* d4 = (float4*)(nps + row * 260) + half * 32;
#pragma unroll
        for (int q = 0; q < 32; q++) d4[q] = s4[q];
    }
    __syncthreads();

    float pb[16], p1[16];
    {
        const float* npi = g_node_p + ((size_t)b * N_SZ + i) * 256;
#pragma unroll
        for (int h = 0; h < 2; h++)
#pragma unroll
            for (int nf = 0; nf < 4; nf++)
#pragma unroll
                for (int v = 0; v < 2; v++) {
                    int idx = h * 8 + nf * 2 + v;
                    int d = wn + (h * 4 + nf) * 8 + (lane & 3) * 2 + v;
                    float bv = bias[d];
                    pb[idx] = bv;
                    p1[idx] = bv + npi[d];
                }
    }

    const float* nps = (const float*)sm;
#pragma unroll
    for (int mf = 0; mf < 4; mf++) {
#pragma unroll
        for (int half = 0; half < 2; half++) {
            int r = wm + mf * 16 + (lane >> 2) + half * 8;
            const float* nj = nps + r * 260 + wn;
#pragma unroll
            for (int h = 0; h < 2; h++) {
                float s = 0.0f;
#pragma unroll
                for (int nf = 0; nf < 4; nf++)
#pragma unroll
                    for (int v = 0; v < 2; v++) {
                        int idx = h * 8 + nf * 2 + v;
                        float a = acc[mf][h * 4 + nf][half * 2 + v];
                        float njv = nj[(h * 4 + nf) * 8 + (lane & 3) * 2 + v];
                        s += (a + p1[idx]) * (a + pb[idx] + njv);
                    }
                s += __shfl_xor_sync(0xffffffffu, s, 1);
                s += __shfl_xor_sync(0xffffffffu, s, 2);
                if ((lane & 3) == 0) {
                    int hg = (wn >> 5) + h;
                    scores[((((size_t)b * NHEAD + hg) * N_SZ + i) << 8) + jt * 128 + r] =
                        10.0f * tanhf(s * 0.17677669529663687f);
                }
            }
        }
    }
}

// ---------------- softmax + AV ----------------
__global__ void softmax_av_kernel(float* __restrict__ attn) {
    const int i = blockIdx.x, h = blockIdx.y, b = blockIdx.z;
    const int tid = threadIdx.x;
    float* row = attn + ((((size_t)(b * NHEAD + h) * N_SZ) + i) << 8);

    __shared__ float sh[16];
    __shared__ float ps[256];
    __shared__ float red[8][33];

    float s = row[tid];
    float m = s;
#pragma unroll
    for (int off = 16; off > 0; off >>= 1)
        m = fmaxf(m, __shfl_xor_sync(0xffffffffu, m, off));
    if ((tid & 31) == 0) sh[tid >> 5] = m;
    __syncthreads();
    float bm = sh[0];
#pragma unroll
    for (int g = 1; g < 8; g++) bm = fmaxf(bm, sh[g]);

    float p = __expf(s - bm);
    float t = p;
#pragma unroll
    for (int off = 16; off > 0; off >>= 1)
        t += __shfl_xor_sync(0xffffffffu, t, off);
    if ((tid & 31) == 0) sh[8 + (tid >> 5)] = t;
    __syncthreads();
    float sum = 0.0f;
#pragma unroll
    for (int g = 0; g < 8; g++) sum += sh[8 + g];

    float a = p * (1.0f / sum);
    row[tid] = a;
    ps[tid] = a;
    __syncthreads();

    const int d = tid & 31, g = tid >> 5;
    const float* np = g_node_p + (size_t)b * N_SZ * D_MODEL + h * 32 + d;
    float acc = 0.0f;
#pragma unroll
    for (int jj = 0; jj < 32; jj++) {
        int j = g * 32 + jj;
        acc = fmaf(ps[j], np[(size_t)j * 256], acc);
    }
    red[g][d] = acc;
    __syncthreads();
    if (tid < 32) {
        float o = 0.0f;
#pragma unroll
        for (int g2 = 0; g2 < 8; g2++) o += red[g2][tid];
        g_out0[((size_t)(b * N_SZ + i)) * D_MODEL + h * 32 + tid] = o;
    }
}

// ---------------- launch ----------------
extern "C" void kernel_launch(void* const* d_in, const int* in_sizes, int n_in,
                              void* d_out, int out_size) {
    const float* nodes = (const float*)d_in[0];
    const float* edges = (const float*)d_in[1];
    const float* W     = (const float*)d_in[2];
    const float* bias  = (const float*)d_in[3];

    float* out  = (float*)d_out;
    float* attn = out + B_SZ * N_SZ * D_MODEL;

    cudaFuncSetAttribute(edge_score_mma, cudaFuncAttributeMaxDynamicSharedMemorySize, SM_DYN);

    wprep_kernel<<<256, 256>>>(W);
    proj_nodes_kernel<<<(B_SZ * N_SZ) / 64, 256>>>(nodes, bias);
    dim3 g2(2, N_SZ, B_SZ);
    edge_score_mma<<<g2, 256, SM_DYN>>>(edges, bias, attn);
    dim3 g3(N_SZ, NHEAD, B_SZ);
    softmax_av_kernel<<<g3, 256>>>(attn);
    proj_final_kernel<<<(B_SZ * N_SZ) / 64, 256>>>(bias, out);
}

// round 5
// speedup vs baseline: 1.9810x; 1.0046x over previous
#include <cuda_runtime.h>
#include <cuda_bf16.h>
#include <math.h>
#include <stdint.h>

#define D_MODEL 256
#define NHEAD   8
#define HEAD_DIM 32
#define B_SZ    4
#define N_SZ    256

// ---------------- device scratch ----------------
__device__ float g_Wt[D_MODEL * D_MODEL];
__device__ float g_node_p[B_SZ * N_SZ * D_MODEL];
__device__ float g_out0[B_SZ * N_SZ * D_MODEL];
// W bf16 splits, pre-swizzled SW128 K-chunk tiles: 4 chunks x [256 n][64 k] (32KB each)
__device__ unsigned char g_WB_hi[131072];
__device__ unsigned char g_WB_lo[131072];

__device__ __forceinline__ uint32_t smem_u32(const void* p) {
    uint32_t a;
    asm("{ .reg .u64 t; cvta.to.shared.u64 t, %1; cvt.u32.u64 %0, t; }" : "=r"(a) : "l"(p));
    return a;
}

__device__ __forceinline__ void ldsm_x4(uint32_t r[4], uint32_t addr) {
    asm volatile("ldmatrix.sync.aligned.m8n8.x4.shared.b16 {%0,%1,%2,%3}, [%4];"
                 : "=r"(r[0]), "=r"(r[1]), "=r"(r[2]), "=r"(r[3]) : "r"(addr));
}

__device__ __forceinline__ void mma_bf16(float c[4], const uint32_t a[4], const uint32_t b[2]) {
    asm volatile(
        "mma.sync.aligned.m16n8k16.row.col.f32.bf16.bf16.f32 "
        "{%0,%1,%2,%3}, {%4,%5,%6,%7}, {%8,%9}, {%0,%1,%2,%3};"
        : "+f"(c[0]), "+f"(c[1]), "+f"(c[2]), "+f"(c[3])
        : "r"(a[0]), "r"(a[1]), "r"(a[2]), "r"(a[3]), "r"(b[0]), "r"(b[1]));
}

// ---------------- prep: W transpose + bf16 split/swizzle (merged) ----------------
__global__ void wprep_kernel(const float* __restrict__ W) {
    int idx = blockIdx.x * 256 + threadIdx.x;  // d*256 + k
    int d = idx >> 8, k = idx & 255;
    float w = W[idx];
    g_Wt[k * 256 + d] = w;
    __nv_bfloat16 h = __float2bfloat16_rn(w);
    float r = w - __bfloat162float(h);
    __nv_bfloat16 l = __float2bfloat16_rn(r);
    int chunk = k >> 6, kc = k & 63;
    int off = d * 128 + kc * 2;
    int sw = off ^ ((off >> 3) & 0x70);
    int pos = chunk * 32768 + sw;
    *(unsigned short*)(g_WB_hi + pos) = __bfloat16_as_ushort(h);
    *(unsigned short*)(g_WB_lo + pos) = __bfloat16_as_ushort(l);
}

// ---------------- fp32 tile GEMM for small projections ----------------
__device__ __forceinline__ void gemm_tile(const float* __restrict__ A, float acc[8][8]) {
    const int tid = threadIdx.x;
    const int tx = tid & 31;
    const int ty = tid >> 5;

    __shared__ float As[2][16][65];
    __shared__ float Ws[2][16][260];

#pragma unroll
    for (int a = 0; a < 8; a++)
#pragma unroll
        for (int c = 0; c < 8; c++) acc[a][c] = 0.0f;

    const int rowL = tid >> 2;
    const int kq = tid & 3;

    {
        float4 v = *(const float4*)(A + rowL * 256 + kq * 4);
        As[0][kq * 4 + 0][rowL] = v.x;
        As[0][kq * 4 + 1][rowL] = v.y;
        As[0][kq * 4 + 2][rowL] = v.z;
        As[0][kq * 4 + 3][rowL] = v.w;
#pragma unroll
        for (int c = 0; c < 4; c++) {
            int f = c * 256 + tid;
            int kk = f >> 6, d4 = f & 63;
            *(float4*)&Ws[0][kk][d4 * 4] = *(const float4*)(g_Wt + kk * 256 + d4 * 4);
        }
    }
    __syncthreads();

#pragma unroll 1
    for (int kt = 0; kt < 16; kt++) {
        const int cur = kt & 1;
        if (kt < 15) {
            const int nxt = cur ^ 1;
            const int k0 = (kt + 1) * 16;
            float4 v = *(const float4*)(A + rowL * 256 + k0 + kq * 4);
            As[nxt][kq * 4 + 0][rowL] = v.x;
            As[nxt][kq * 4 + 1][rowL] = v.y;
            As[nxt][kq * 4 + 2][rowL] = v.z;
            As[nxt][kq * 4 + 3][rowL] = v.w;
#pragma unroll
            for (int c = 0; c < 4; c++) {
                int f = c * 256 + tid;
                int kk = f >> 6, d4 = f & 63;
                *(float4*)&Ws[nxt][kk][d4 * 4] = *(const float4*)(g_Wt + (k0 + kk) * 256 + d4 * 4);
            }
        }
#pragma unroll
        for (int kk = 0; kk < 16; kk++) {
            float a[8], w[8];
#pragma unroll
            for (int jj = 0; jj < 8; jj++) a[jj] = As[cur][kk][jj * 8 + ty];
#pragma unroll
            for (int u = 0; u < 8; u++) w[u] = Ws[cur][kk][u * 32 + tx];
#pragma unroll
            for (int jj = 0; jj < 8; jj++)
#pragma unroll
                for (int u = 0; u < 8; u++)
                    acc[jj][u] = fmaf(a[jj], w[u], acc[jj][u]);
        }
        __syncthreads();
    }
}

__global__ void __launch_bounds__(256, 2)
proj_nodes_kernel(const float* __restrict__ nodes, const float* __restrict__ bias) {
    float acc[8][8];
    gemm_tile(nodes + (size_t)blockIdx.x * 64 * 256, acc);
    const int tx = threadIdx.x & 31, ty = threadIdx.x >> 5;
#pragma unroll
    for (int jj = 0; jj < 8; jj++) {
        int r = blockIdx.x * 64 + jj * 8 + ty;
#pragma unroll
        for (int u = 0; u < 8; u++)
            g_node_p[r * 256 + u * 32 + tx] = acc[jj][u] + bias[u * 32 + tx];
    }
}

__global__ void __launch_bounds__(256, 2)
proj_final_kernel(const float* __restrict__ bias, float* __restrict__ out) {
    float acc[8][8];
    gemm_tile(g_out0 + (size_t)blockIdx.x * 64 * 256, acc);
    const int tx = threadIdx.x & 31, ty = threadIdx.x >> 5;
#pragma unroll
    for (int jj = 0; jj < 8; jj++) {
        int r = blockIdx.x * 64 + jj * 8 + ty;
#pragma unroll
        for (int u = 0; u < 8; u++)
            out[r * 256 + u * 32 + tx] = acc[jj][u] + bias[u * 32 + tx];
    }
}

// ---------------- edge projection + scores: 512 threads, warp tile 64x32 ----------------
// SMEM: A slots: 2 x (16KB hi + 16KB lo)  @ 0        (64KB)
//       W slots: 2 x (32KB hi + 32KB lo)  @ 65536    (128KB)
#define SM_A   0
#define SM_W   65536
#define SM_DYN 196608
#define NTHR   512

__device__ __forceinline__ void copyW_async(uint32_t smb, int c, int slot) {
    const int t = threadIdx.x;
    unsigned long long sh = (unsigned long long)__cvta_generic_to_global(g_WB_hi) + c * 32768;
    unsigned long long sl = (unsigned long long)__cvta_generic_to_global(g_WB_lo) + c * 32768;
    uint32_t dh = smb + SM_W + slot * 65536;
    uint32_t dl = dh + 32768;
#pragma unroll
    for (int q = 0; q < 4; q++) {
        int off = (q * NTHR + t) * 16;
        asm volatile("cp.async.cg.shared.global [%0], [%1], 16;" :: "r"(dh + off), "l"(sh + off));
        asm volatile("cp.async.cg.shared.global [%0], [%1], 16;" :: "r"(dl + off), "l"(sl + off));
    }
    asm volatile("cp.async.commit_group;" ::: "memory");
}

// convert one float4 of A-chunk data and store hi/lo swizzled into A slot
__device__ __forceinline__ void cvt_store_a(char* sm, int slot, int flat, float4 v) {
    __nv_bfloat16 hx = __float2bfloat16_rn(v.x);
    __nv_bfloat16 hy = __float2bfloat16_rn(v.y);
    __nv_bfloat16 hz = __float2bfloat16_rn(v.z);
    __nv_bfloat16 hw = __float2bfloat16_rn(v.w);
    __nv_bfloat16 lx = __float2bfloat16_rn(v.x - __bfloat162float(hx));
    __nv_bfloat16 ly = __float2bfloat16_rn(v.y - __bfloat162float(hy));
    __nv_bfloat16 lz = __float2bfloat16_rn(v.z - __bfloat162float(hz));
    __nv_bfloat16 lw = __float2bfloat16_rn(v.w - __bfloat162float(hw));
    uint2 hi2, lo2;
    hi2.x = (uint32_t)__bfloat16_as_ushort(hx) | ((uint32_t)__bfloat16_as_ushort(hy) << 16);
    hi2.y = (uint32_t)__bfloat16_as_ushort(hz) | ((uint32_t)__bfloat16_as_ushort(hw) << 16);
    lo2.x = (uint32_t)__bfloat16_as_ushort(lx) | ((uint32_t)__bfloat16_as_ushort(ly) << 16);
    lo2.y = (uint32_t)__bfloat16_as_ushort(lz) | ((uint32_t)__bfloat16_as_ushort(lw) << 16);
    int row = flat >> 4, c4 = flat & 15;
    int off = row * 128 + c4 * 8;
    int sw = off ^ ((off >> 3) & 0x70);
    char* base = sm + SM_A + slot * 32768;
    *(uint2*)(base + sw) = hi2;
    *(uint2*)(base + 16384 + sw) = lo2;
}

__global__ void __launch_bounds__(NTHR, 1)
edge_score_mma(const float* __restrict__ edges, const float* __restrict__ bias,
               float* __restrict__ scores) {
    extern __shared__ char sm[];
    const uint32_t smb = smem_u32(sm);
    const int tid = threadIdx.x, wid = tid >> 5, lane = tid & 31;
    const int jt = blockIdx.x, i = blockIdx.y, b = blockIdx.z;
    const int wm = (wid >> 3) * 64;      // 2 m-groups of 64 rows
    const int wn = (wid & 7) * 32;       // 8 n-groups of 32 cols = one head each

    const float* A = edges + ((((size_t)b * N_SZ + i) * N_SZ) + (size_t)jt * 128) * D_MODEL;

    // ---- prologue: W chunk 0 (async) + A chunk 0 (convert) ----
    copyW_async(smb, 0, 0);
#pragma unroll
    for (int q = 0; q < 4; q++) {
        int flat = q * NTHR + tid;
        int row = flat >> 4, c4 = flat & 15;
        float4 v = *(const float4*)(A + (size_t)row * 256 + c4 * 4);
        cvt_store_a(sm, 0, flat, v);
    }
    asm volatile("cp.async.wait_group 0;" ::: "memory");
    __syncthreads();

    float acc[4][4][4];
#pragma unroll
    for (int mf = 0; mf < 4; mf++)
#pragma unroll
        for (int nf = 0; nf < 4; nf++)
#pragma unroll
            for (int c = 0; c < 4; c++) acc[mf][nf][c] = 0.0f;

    uint32_t apre[4], axor[4];
#pragma unroll
    for (int mf = 0; mf < 4; mf++) {
        int row = wm + mf * 16 + (lane & 15);
        apre[mf] = row * 128;
        axor[mf] = (row & 7) << 4;
    }
    const int koffA = (lane >> 4) * 8;
    uint32_t bpre[2], bxor[2];
#pragma unroll
    for (int gb = 0; gb < 2; gb++) {
        int n = wn + gb * 16 + (((lane >> 3) >= 2) ? 8 : 0) + (lane & 7);
        bpre[gb] = n * 128;
        bxor[gb] = (n & 7) << 4;
    }
    const int kcB = ((lane >> 3) & 1) * 8;

#pragma unroll 1
    for (int ch = 0; ch < 4; ch++) {
        const int cur = ch & 1, nxt = cur ^ 1;
        if (ch < 3) copyW_async(smb, ch + 1, nxt);
        const uint32_t abase = smb + SM_A + cur * 32768;
        const uint32_t wbase = smb + SM_W + cur * 65536;
        const float* Anext = A + (ch + 1) * 64;

#pragma unroll
        for (int ks = 0; ks < 4; ks++) {
            // prefetch next-chunk A fp32 (1 float4/thread/ks)
            float4 v0;
            int f0 = ks * NTHR + tid;
            if (ch < 3)
                v0 = *(const float4*)(Anext + (size_t)(f0 >> 4) * 256 + (f0 & 15) * 4);

            // B fragments for this ks (one head-pair worth, reused by 4 mf)
            const uint32_t kc2 = (uint32_t)((ks * 16 + kcB) * 2);
            uint32_t bh[2][4], bl[2][4];
#pragma unroll
            for (int gb = 0; gb < 2; gb++) {
                uint32_t bd = wbase + bpre[gb] + (kc2 ^ bxor[gb]);
                ldsm_x4(bh[gb], bd);
                ldsm_x4(bl[gb], bd + 32768);
            }
            const uint32_t kg2 = (uint32_t)((ks * 16 + koffA) * 2);
#pragma unroll
            for (int mf = 0; mf < 4; mf++) {
                uint32_t ah[4], al[4];
                uint32_t ad = abase + apre[mf] + (kg2 ^ axor[mf]);
                ldsm_x4(ah, ad);
                ldsm_x4(al, ad + 16384);
#pragma unroll
                for (int nf = 0; nf < 4; nf++) {
                    const uint32_t* ph = &bh[nf >> 1][(nf & 1) * 2];
                    const uint32_t* pl = &bl[nf >> 1][(nf & 1) * 2];
                    mma_bf16(acc[mf][nf], ah, ph);
                    mma_bf16(acc[mf][nf], ah, pl);
                    mma_bf16(acc[mf][nf], al, ph);
                }
            }

            if (ch < 3) cvt_store_a(sm, nxt, f0, v0);
        }
        asm volatile("cp.async.wait_group 0;" ::: "memory");
        __syncthreads();
    }

    // ---- epilogue: stage np_j tile (fp32, stride 260) ----
    {
        float* nps = (float*)sm;
        const float* src = g_node_p + ((size_t)b * N_SZ + jt * 128) * 256;
        int row = tid >> 2, q4 = tid & 3;
        const float4* s4 = (const float4*)(src + (size_t)row * 256) + q4 * 16;
        float4* d4 = (float4*)(nps + row * 260) + q4 * 16;
#pragma unroll
        for (int q = 0; q < 16; q++) d4[q] = s4[q];
    }
    __syncthreads();

    // per-thread bias/np_i constants for this warp's head (8 cols/thread)
    float pb[8], p1[8];
    {
        const float* npi = g_node_p + ((size_t)b * N_SZ + i) * 256;
#pragma unroll
        for (int nf = 0; nf < 4; nf++)
#pragma unroll
            for (int v = 0; v < 2; v++) {
                int idx = nf * 2 + v;
                int d = wn + nf * 8 + (lane & 3) * 2 + v;
                float bv = bias[d];
                pb[idx] = bv;
                p1[idx] = bv + npi[d];
            }
    }

    const int hg = wid & 7;
    const float* nps = (const float*)sm;
#pragma unroll
    for (int mf = 0; mf < 4; mf++) {
#pragma unroll
        for (int half = 0; half < 2; half++) {
            int r = wm + mf * 16 + (lane >> 2) + half * 8;
            const float* nj = nps + r * 260 + wn;
            float s = 0.0f;
#pragma unroll
            for (int nf = 0; nf < 4; nf++)
#pragma unroll
                for (int v = 0; v < 2; v++) {
                    int idx = nf * 2 + v;
                    float a = acc[mf][nf][half * 2 + v];
                    float njv = nj[nf * 8 + (lane & 3) * 2 + v];
                    s += (a + p1[idx]) * (a + pb[idx] + njv);
                }
            s += __shfl_xor_sync(0xffffffffu, s, 1);
            s += __shfl_xor_sync(0xffffffffu, s, 2);
            if ((lane & 3) == 0) {
                scores[((((size_t)b * NHEAD + hg) * N_SZ + i) << 8) + jt * 128 + r] =
                    10.0f * tanhf(s * 0.17677669529663687f);
            }
        }
    }
}

// ---------------- softmax + AV ----------------
__global__ void softmax_av_kernel(float* __restrict__ attn) {
    const int i = blockIdx.x, h = blockIdx.y, b = blockIdx.z;
    const int tid = threadIdx.x;
    float* row = attn + ((((size_t)(b * NHEAD + h) * N_SZ) + i) << 8);

    __shared__ float sh[16];
    __shared__ float ps[256];
    __shared__ float red[8][33];

    float s = row[tid];
    float m = s;
#pragma unroll
    for (int off = 16; off > 0; off >>= 1)
        m = fmaxf(m, __shfl_xor_sync(0xffffffffu, m, off));
    if ((tid & 31) == 0) sh[tid >> 5] = m;
    __syncthreads();
    float bm = sh[0];
#pragma unroll
    for (int g = 1; g < 8; g++) bm = fmaxf(bm, sh[g]);

    float p = __expf(s - bm);
    float t = p;
#pragma unroll
    for (int off = 16; off > 0; off >>= 1)
        t += __shfl_xor_sync(0xffffffffu, t, off);
    if ((tid & 31) == 0) sh[8 + (tid >> 5)] = t;
    __syncthreads();
    float sum = 0.0f;
#pragma unroll
    for (int g = 0; g < 8; g++) sum += sh[8 + g];

    float a = p * (1.0f / sum);
    row[tid] = a;
    ps[tid] = a;
    __syncthreads();

    const int d = tid & 31, g = tid >> 5;
    const float* np = g_node_p + (size_t)b * N_SZ * D_MODEL + h * 32 + d;
    float acc = 0.0f;
#pragma unroll
    for (int jj = 0; jj < 32; jj++) {
        int j = g * 32 + jj;
        acc = fmaf(ps[j], np[(size_t)j * 256], acc);
    }
    red[g][d] = acc;
    __syncthreads();
    if (tid < 32) {
        float o = 0.0f;
#pragma unroll
        for (int g2 = 0; g2 < 8; g2++) o += red[g2][tid];
        g_out0[((size_t)(b * N_SZ + i)) * D_MODEL + h * 32 + tid] = o;
    }
}

// ---------------- launch ----------------
extern "C" void kernel_launch(void* const* d_in, const int* in_sizes, int n_in,
                              void* d_out, int out_size) {
    const float* nodes = (const float*)d_in[0];
    const float* edges = (const float*)d_in[1];
    const float* W     = (const float*)d_in[2];
    const float* bias  = (const float*)d_in[3];

    float* out  = (float*)d_out;
    float* attn = out + B_SZ * N_SZ * D_MODEL;

    cudaFuncSetAttribute(edge_score_mma, cudaFuncAttributeMaxDynamicSharedMemorySize, SM_DYN);

    wprep_kernel<<<256, 256>>>(W);
    proj_nodes_kernel<<<(B_SZ * N_SZ) / 64, 256>>>(nodes, bias);
    dim3 g2(2, N_SZ, B_SZ);
    edge_score_mma<<<g2, NTHR, SM_DYN>>>(edges, bias, attn);
    dim3 g3(N_SZ, NHEAD, B_SZ);
    softmax_av_kernel<<<g3, 256>>>(attn);
    proj_final_kernel<<<(B_SZ * N_SZ) / 64, 256>>>(bias, out);
}

// round 6
// speedup vs baseline: 1.9912x; 1.0052x over previous
#include <cuda_runtime.h>
#include <cuda_bf16.h>
#include <math.h>
#include <stdint.h>

#define D_MODEL 256
#define NHEAD   8
#define HEAD_DIM 32
#define B_SZ    4
#define N_SZ    256

// ---------------- device scratch ----------------
__device__ float g_Wt[D_MODEL * D_MODEL];
__device__ float g_node_p[B_SZ * N_SZ * D_MODEL];
__device__ float g_out0[B_SZ * N_SZ * D_MODEL];
// W bf16 splits, pre-swizzled SW128 K-chunk tiles: 4 chunks x [256 n][64 k] (32KB each)
__device__ __align__(128) unsigned char g_WB_hi[131072];
__device__ __align__(128) unsigned char g_WB_lo[131072];

__device__ __forceinline__ uint32_t smem_u32(const void* p) {
    uint32_t a;
    asm("{ .reg .u64 t; cvta.to.shared.u64 t, %1; cvt.u32.u64 %0, t; }" : "=r"(a) : "l"(p));
    return a;
}

__device__ __forceinline__ void ldsm_x4(uint32_t r[4], uint32_t addr) {
    asm volatile("ldmatrix.sync.aligned.m8n8.x4.shared.b16 {%0,%1,%2,%3}, [%4];"
                 : "=r"(r[0]), "=r"(r[1]), "=r"(r[2]), "=r"(r[3]) : "r"(addr));
}

__device__ __forceinline__ void mma_bf16(float c[4], const uint32_t a[4], const uint32_t b[2]) {
    asm volatile(
        "mma.sync.aligned.m16n8k16.row.col.f32.bf16.bf16.f32 "
        "{%0,%1,%2,%3}, {%4,%5,%6,%7}, {%8,%9}, {%0,%1,%2,%3};"
        : "+f"(c[0]), "+f"(c[1]), "+f"(c[2]), "+f"(c[3])
        : "r"(a[0]), "r"(a[1]), "r"(a[2]), "r"(a[3]), "r"(b[0]), "r"(b[1]));
}

// mbarrier helpers (compile-verified pattern from round 2)
#define MBAR_INIT(mbar, cnt) \
    asm volatile("mbarrier.init.shared.b64 [%0], %1;" :: "r"((uint32_t)(mbar)), "r"((uint32_t)(cnt)) : "memory")
#define MBAR_EXPECT_TX(mbar, tx) \
    asm volatile("mbarrier.arrive.expect_tx.shared.b64 _, [%0], %1;" :: "r"((uint32_t)(mbar)), "r"((uint32_t)(tx)) : "memory")
#define MBAR_WAIT(mbar, parity) do {                                          \
    uint32_t _m = (uint32_t)(mbar); uint32_t _p = (uint32_t)(parity);         \
    asm volatile(                                                             \
        "{\n\t.reg .pred P1;\n\t"                                             \
        "WAIT_LOOP_%=:\n\t"                                                   \
        "mbarrier.try_wait.parity.acquire.cta.shared::cta.b64 P1, [%0], %1, 0x989680;\n\t" \
        "@P1 bra.uni WAIT_DONE_%=;\n\t"                                       \
        "bra.uni WAIT_LOOP_%=;\n\t"                                           \
        "WAIT_DONE_%=:\n\t}"                                                  \
        :: "r"(_m), "r"(_p) : "memory");                                      \
} while (0)
// 1D bulk copy gmem->smem (UBLKCP), completion via mbarrier tx bytes
#define BULK_G2S(dst, src, bytes, mbar) \
    asm volatile("cp.async.bulk.shared::cta.global.mbarrier::complete_tx::bytes [%0], [%1], %2, [%3];" \
                 :: "r"((uint32_t)(dst)), "l"(src), "r"((uint32_t)(bytes)), "r"((uint32_t)(mbar)) : "memory")

// ---------------- prep: W transpose + bf16 split/swizzle ----------------
__global__ void wprep_kernel(const float* __restrict__ W) {
    int idx = blockIdx.x * 256 + threadIdx.x;  // d*256 + k
    int d = idx >> 8, k = idx & 255;
    float w = W[idx];
    g_Wt[k * 256 + d] = w;
    __nv_bfloat16 h = __float2bfloat16_rn(w);
    float r = w - __bfloat162float(h);
    __nv_bfloat16 l = __float2bfloat16_rn(r);
    int chunk = k >> 6, kc = k & 63;
    int off = d * 128 + kc * 2;
    int sw = off ^ ((off >> 3) & 0x70);
    int pos = chunk * 32768 + sw;
    *(unsigned short*)(g_WB_hi + pos) = __bfloat16_as_ushort(h);
    *(unsigned short*)(g_WB_lo + pos) = __bfloat16_as_ushort(l);
}

// ---------------- fp32 tile GEMM for small projections ----------------
__device__ __forceinline__ void gemm_tile(const float* __restrict__ A, float acc[8][8]) {
    const int tid = threadIdx.x;
    const int tx = tid & 31;
    const int ty = tid >> 5;

    __shared__ float As[2][16][65];
    __shared__ float Ws[2][16][260];

#pragma unroll
    for (int a = 0; a < 8; a++)
#pragma unroll
        for (int c = 0; c < 8; c++) acc[a][c] = 0.0f;

    const int rowL = tid >> 2;
    const int kq = tid & 3;

    {
        float4 v = *(const float4*)(A + rowL * 256 + kq * 4);
        As[0][kq * 4 + 0][rowL] = v.x;
        As[0][kq * 4 + 1][rowL] = v.y;
        As[0][kq * 4 + 2][rowL] = v.z;
        As[0][kq * 4 + 3][rowL] = v.w;
#pragma unroll
        for (int c = 0; c < 4; c++) {
            int f = c * 256 + tid;
            int kk = f >> 6, d4 = f & 63;
            *(float4*)&Ws[0][kk][d4 * 4] = *(const float4*)(g_Wt + kk * 256 + d4 * 4);
        }
    }
    __syncthreads();

#pragma unroll 1
    for (int kt = 0; kt < 16; kt++) {
        const int cur = kt & 1;
        if (kt < 15) {
            const int nxt = cur ^ 1;
            const int k0 = (kt + 1) * 16;
            float4 v = *(const float4*)(A + rowL * 256 + k0 + kq * 4);
            As[nxt][kq * 4 + 0][rowL] = v.x;
            As[nxt][kq * 4 + 1][rowL] = v.y;
            As[nxt][kq * 4 + 2][rowL] = v.z;
            As[nxt][kq * 4 + 3][rowL] = v.w;
#pragma unroll
            for (int c = 0; c < 4; c++) {
                int f = c * 256 + tid;
                int kk = f >> 6, d4 = f & 63;
                *(float4*)&Ws[nxt][kk][d4 * 4] = *(const float4*)(g_Wt + (k0 + kk) * 256 + d4 * 4);
            }
        }
#pragma unroll
        for (int kk = 0; kk < 16; kk++) {
            float a[8], w[8];
#pragma unroll
            for (int jj = 0; jj < 8; jj++) a[jj] = As[cur][kk][jj * 8 + ty];
#pragma unroll
            for (int u = 0; u < 8; u++) w[u] = Ws[cur][kk][u * 32 + tx];
#pragma unroll
            for (int jj = 0; jj < 8; jj++)
#pragma unroll
                for (int u = 0; u < 8; u++)
                    acc[jj][u] = fmaf(a[jj], w[u], acc[jj][u]);
        }
        __syncthreads();
    }
}

__global__ void __launch_bounds__(256, 2)
proj_nodes_kernel(const float* __restrict__ nodes, const float* __restrict__ bias) {
    float acc[8][8];
    gemm_tile(nodes + (size_t)blockIdx.x * 64 * 256, acc);
    const int tx = threadIdx.x & 31, ty = threadIdx.x >> 5;
#pragma unroll
    for (int jj = 0; jj < 8; jj++) {
        int r = blockIdx.x * 64 + jj * 8 + ty;
#pragma unroll
        for (int u = 0; u < 8; u++)
            g_node_p[r * 256 + u * 32 + tx] = acc[jj][u] + bias[u * 32 + tx];
    }
}

__global__ void __launch_bounds__(256, 2)
proj_final_kernel(const float* __restrict__ bias, float* __restrict__ out) {
    float acc[8][8];
    gemm_tile(g_out0 + (size_t)blockIdx.x * 64 * 256, acc);
    const int tx = threadIdx.x & 31, ty = threadIdx.x >> 5;
#pragma unroll
    for (int jj = 0; jj < 8; jj++) {
        int r = blockIdx.x * 64 + jj * 8 + ty;
#pragma unroll
        for (int u = 0; u < 8; u++)
            out[r * 256 + u * 32 + tx] = acc[jj][u] + bias[u * 32 + tx];
    }
}

// ---------------- edge projection + scores ----------------
// SMEM: A slots: 2 x (16KB hi + 16KB lo)  @ 0        (64KB)
//       W slots: 2 x (32KB hi + 32KB lo)  @ 65536    (128KB)
#define SM_A   0
#define SM_W   65536
#define SM_DYN 196608
#define NTHR   512

__device__ __forceinline__ void cvt_store_a(char* sm, int slot, int flat, float4 v) {
    __nv_bfloat16 hx = __float2bfloat16_rn(v.x);
    __nv_bfloat16 hy = __float2bfloat16_rn(v.y);
    __nv_bfloat16 hz = __float2bfloat16_rn(v.z);
    __nv_bfloat16 hw = __float2bfloat16_rn(v.w);
    __nv_bfloat16 lx = __float2bfloat16_rn(v.x - __bfloat162float(hx));
    __nv_bfloat16 ly = __float2bfloat16_rn(v.y - __bfloat162float(hy));
    __nv_bfloat16 lz = __float2bfloat16_rn(v.z - __bfloat162float(hz));
    __nv_bfloat16 lw = __float2bfloat16_rn(v.w - __bfloat162float(hw));
    uint2 hi2, lo2;
    hi2.x = (uint32_t)__bfloat16_as_ushort(hx) | ((uint32_t)__bfloat16_as_ushort(hy) << 16);
    hi2.y = (uint32_t)__bfloat16_as_ushort(hz) | ((uint32_t)__bfloat16_as_ushort(hw) << 16);
    lo2.x = (uint32_t)__bfloat16_as_ushort(lx) | ((uint32_t)__bfloat16_as_ushort(ly) << 16);
    lo2.y = (uint32_t)__bfloat16_as_ushort(lz) | ((uint32_t)__bfloat16_as_ushort(lw) << 16);
    int row = flat >> 4, c4 = flat & 15;
    int off = row * 128 + c4 * 8;
    int sw = off ^ ((off >> 3) & 0x70);
    char* base = sm + SM_A + slot * 32768;
    *(uint2*)(base + sw) = hi2;
    *(uint2*)(base + 16384 + sw) = lo2;
}

__global__ void __launch_bounds__(NTHR, 1)
edge_score_mma(const float* __restrict__ edges, const float* __restrict__ bias,
               float* __restrict__ scores) {
    extern __shared__ char sm[];
    __shared__ __align__(8) unsigned long long mbarr[2];
    const uint32_t smb = smem_u32(sm);
    const uint32_t mb0 = smem_u32(&mbarr[0]);
    const int tid = threadIdx.x, wid = tid >> 5, lane = tid & 31;
    const int jt = blockIdx.x, i = blockIdx.y, b = blockIdx.z;
    const int wm = (wid >> 3) * 64;
    const int wn = (wid & 7) * 32;

    const float* A = edges + ((((size_t)b * N_SZ + i) * N_SZ) + (size_t)jt * 128) * D_MODEL;
    const unsigned long long gwh = (unsigned long long)__cvta_generic_to_global(g_WB_hi);
    const unsigned long long gwl = (unsigned long long)__cvta_generic_to_global(g_WB_lo);

    if (tid == 0) {
        MBAR_INIT(mb0, 1);
        MBAR_INIT(mb0 + 8, 1);
    }
    __syncthreads();

    // ---- prologue: bulk W chunk 0 -> slot 0; convert A chunk 0 ----
    if (tid == 0) {
        MBAR_EXPECT_TX(mb0, 65536);
        BULK_G2S(smb + SM_W, gwh, 32768, mb0);
        BULK_G2S(smb + SM_W + 32768, gwl, 32768, mb0);
    }
#pragma unroll
    for (int q = 0; q < 4; q++) {
        int flat = q * NTHR + tid;
        int row = flat >> 4, c4 = flat & 15;
        float4 v = *(const float4*)(A + (size_t)row * 256 + c4 * 4);
        cvt_store_a(sm, 0, flat, v);
    }
    __syncthreads();

    float acc[4][4][4];
#pragma unroll
    for (int mf = 0; mf < 4; mf++)
#pragma unroll
        for (int nf = 0; nf < 4; nf++)
#pragma unroll
            for (int c = 0; c < 4; c++) acc[mf][nf][c] = 0.0f;

    uint32_t apre[4], axor[4];
#pragma unroll
    for (int mf = 0; mf < 4; mf++) {
        int row = wm + mf * 16 + (lane & 15);
        apre[mf] = row * 128;
        axor[mf] = (row & 7) << 4;
    }
    const int koffA = (lane >> 4) * 8;
    uint32_t bpre[2], bxor[2];
#pragma unroll
    for (int gb = 0; gb < 2; gb++) {
        int n = wn + gb * 16 + (((lane >> 3) >= 2) ? 8 : 0) + (lane & 7);
        bpre[gb] = n * 128;
        bxor[gb] = (n & 7) << 4;
    }
    const int kcB = ((lane >> 3) & 1) * 8;

#pragma unroll 1
    for (int ch = 0; ch < 4; ch++) {
        const int cur = ch & 1, nxt = cur ^ 1;
        // issue next W chunk bulk copy (off-LSU)
        if (ch < 3 && tid == 0) {
            MBAR_EXPECT_TX(mb0 + 8 * nxt, 65536);
            BULK_G2S(smb + SM_W + nxt * 65536, gwh + (ch + 1) * 32768, 32768, mb0 + 8 * nxt);
            BULK_G2S(smb + SM_W + nxt * 65536 + 32768, gwl + (ch + 1) * 32768, 32768, mb0 + 8 * nxt);
        }
        // prefetch next A chunk fp32 (4 x LDG.128, high MLP, consumed at chunk end)
        float4 v[4];
        if (ch < 3) {
            const float* Anext = A + (ch + 1) * 64;
#pragma unroll
            for (int q = 0; q < 4; q++) {
                int flat = q * NTHR + tid;
                v[q] = *(const float4*)(Anext + (size_t)(flat >> 4) * 256 + (flat & 15) * 4);
            }
        }
        // wait for this chunk's W
        MBAR_WAIT(mb0 + 8 * cur, ch >> 1);

        const uint32_t abase = smb + SM_A + cur * 32768;
        const uint32_t wbase = smb + SM_W + cur * 65536;
#pragma unroll
        for (int ks = 0; ks < 4; ks++) {
            const uint32_t kc2 = (uint32_t)((ks * 16 + kcB) * 2);
            uint32_t bh[2][4], bl[2][4];
#pragma unroll
            for (int gb = 0; gb < 2; gb++) {
                uint32_t bd = wbase + bpre[gb] + (kc2 ^ bxor[gb]);
                ldsm_x4(bh[gb], bd);
                ldsm_x4(bl[gb], bd + 32768);
            }
            const uint32_t kg2 = (uint32_t)((ks * 16 + koffA) * 2);
#pragma unroll
            for (int mf = 0; mf < 4; mf++) {
                uint32_t ah[4], al[4];
                uint32_t ad = abase + apre[mf] + (kg2 ^ axor[mf]);
                ldsm_x4(ah, ad);
                ldsm_x4(al, ad + 16384);
#pragma unroll
                for (int nf = 0; nf < 4; nf++) {
                    const uint32_t* ph = &bh[nf >> 1][(nf & 1) * 2];
                    const uint32_t* pl = &bl[nf >> 1][(nf & 1) * 2];
                    mma_bf16(acc[mf][nf], ah, ph);
                    mma_bf16(acc[mf][nf], ah, pl);
                    mma_bf16(acc[mf][nf], al, ph);
                }
            }
        }
        // convert+store next A chunk
        if (ch < 3) {
#pragma unroll
            for (int q = 0; q < 4; q++)
                cvt_store_a(sm, nxt, q * NTHR + tid, v[q]);
        }
        __syncthreads();
    }

    // ---- epilogue: stage np_j tile (fp32, stride 260) ----
    {
        float* nps = (float*)sm;
        const float* src = g_node_p + ((size_t)b * N_SZ + jt * 128) * 256;
        int row = tid >> 2, q4 = tid & 3;
        const float4* s4 = (const float4*)(src + (size_t)row * 256) + q4 * 16;
        float4* d4 = (float4*)(nps + row * 260) + q4 * 16;
#pragma unroll
        for (int q = 0; q < 16; q++) d4[q] = s4[q];
    }
    __syncthreads();

    float pb[8], p1[8];
    {
        const float* npi = g_node_p + ((size_t)b * N_SZ + i) * 256;
#pragma unroll
        for (int nf = 0; nf < 4; nf++)
#pragma unroll
            for (int v2 = 0; v2 < 2; v2++) {
                int idx = nf * 2 + v2;
                int d = wn + nf * 8 + (lane & 3) * 2 + v2;
                float bv = bias[d];
                pb[idx] = bv;
                p1[idx] = bv + npi[d];
            }
    }

    const int hg = wid & 7;
    const float* nps = (const float*)sm;
#pragma unroll
    for (int mf = 0; mf < 4; mf++) {
#pragma unroll
        for (int half = 0; half < 2; half++) {
            int r = wm + mf * 16 + (lane >> 2) + half * 8;
            const float* nj = nps + r * 260 + wn;
            float s = 0.0f;
#pragma unroll
            for (int nf = 0; nf < 4; nf++)
#pragma unroll
                for (int v2 = 0; v2 < 2; v2++) {
                    int idx = nf * 2 + v2;
                    float a = acc[mf][nf][half * 2 + v2];
                    float njv = nj[nf * 8 + (lane & 3) * 2 + v2];
                    s += (a + p1[idx]) * (a + pb[idx] + njv);
                }
            s += __shfl_xor_sync(0xffffffffu, s, 1);
            s += __shfl_xor_sync(0xffffffffu, s, 2);
            if ((lane & 3) == 0) {
                scores[((((size_t)b * NHEAD + hg) * N_SZ + i) << 8) + jt * 128 + r] =
                    10.0f * tanhf(s * 0.17677669529663687f);
            }
        }
    }
}

// ---------------- softmax + AV ----------------
__global__ void softmax_av_kernel(float* __restrict__ attn) {
    const int i = blockIdx.x, h = blockIdx.y, b = blockIdx.z;
    const int tid = threadIdx.x;
    float* row = attn + ((((size_t)(b * NHEAD + h) * N_SZ) + i) << 8);

    __shared__ float sh[16];
    __shared__ float ps[256];
    __shared__ float red[8][33];

    float s = row[tid];
    float m = s;
#pragma unroll
    for (int off = 16; off > 0; off >>= 1)
        m = fmaxf(m, __shfl_xor_sync(0xffffffffu, m, off));
    if ((tid & 31) == 0) sh[tid >> 5] = m;
    __syncthreads();
    float bm = sh[0];
#pragma unroll
    for (int g = 1; g < 8; g++) bm = fmaxf(bm, sh[g]);

    float p = __expf(s - bm);
    float t = p;
#pragma unroll
    for (int off = 16; off > 0; off >>= 1)
        t += __shfl_xor_sync(0xffffffffu, t, off);
    if ((tid & 31) == 0) sh[8 + (tid >> 5)] = t;
    __syncthreads();
    float sum = 0.0f;
#pragma unroll
    for (int g = 0; g < 8; g++) sum += sh[8 + g];

    float a = p * (1.0f / sum);
    row[tid] = a;
    ps[tid] = a;
    __syncthreads();

    const int d = tid & 31, g = tid >> 5;
    const float* np = g_node_p + (size_t)b * N_SZ * D_MODEL + h * 32 + d;
    float acc = 0.0f;
#pragma unroll
    for (int jj = 0; jj < 32; jj++) {
        int j = g * 32 + jj;
        acc = fmaf(ps[j], np[(size_t)j * 256], acc);
    }
    red[g][d] = acc;
    __syncthreads();
    if (tid < 32) {
        float o = 0.0f;
#pragma unroll
        for (int g2 = 0; g2 < 8; g2++) o += red[g2][tid];
        g_out0[((size_t)(b * N_SZ + i)) * D_MODEL + h * 32 + tid] = o;
    }
}

// ---------------- launch ----------------
extern "C" void kernel_launch(void* const* d_in, const int* in_sizes, int n_in,
                              void* d_out, int out_size) {
    const float* nodes = (const float*)d_in[0];
    const float* edges = (const float*)d_in[1];
    const float* W     = (const float*)d_in[2];
    const float* bias  = (const float*)d_in[3];

    float* out  = (float*)d_out;
    float* attn = out + B_SZ * N_SZ * D_MODEL;

    cudaFuncSetAttribute(edge_score_mma, cudaFuncAttributeMaxDynamicSharedMemorySize, SM_DYN);

    wprep_kernel<<<256, 256>>>(W);
    proj_nodes_kernel<<<(B_SZ * N_SZ) / 64, 256>>>(nodes, bias);
    dim3 g2(2, N_SZ, B_SZ);
    edge_score_mma<<<g2, NTHR, SM_DYN>>>(edges, bias, attn);
    dim3 g3(N_SZ, NHEAD, B_SZ);
    softmax_av_kernel<<<g3, 256>>>(attn);
    proj_final_kernel<<<(B_SZ * N_SZ) / 64, 256>>>(bias, out);
}